// round 4
// baseline (speedup 1.0000x reference)
#include <cuda_runtime.h>
#include <cuda_bf16.h>
#include <cstdint>

// ---------------- problem constants ----------------
#define K2     36864
#define MTOT   1024
#define NTOT   768
#define SPLITK 6
#define KS     (K2 / SPLITK)      // 6144 k per CTA
#define BM     128
#define BN     256
#define BK     64                 // bf16 k per pipeline stage (128B rows)
#define NIT    (KS / BK)          // 96
#define NSTAGE 2

#define BATCH   64
#define T_IN    12
#define HORIZON 12

// ---------------- device scratch ----------------
__device__ __nv_bfloat16 g_Ahi[(size_t)MTOT * K2];
__device__ __nv_bfloat16 g_Alo[(size_t)MTOT * K2];
__device__ __nv_bfloat16 g_Bhi[(size_t)NTOT * K2];
__device__ __nv_bfloat16 g_Blo[(size_t)NTOT * K2];
__device__ float g_part[(size_t)SPLITK * MTOT * NTOT];   // [s][m][n]

// ---------------- SMEM layout ----------------
// per stage: Ahi 16K | Alo 16K | Bhi 32K | Blo 32K = 96K; 2 stages = 192K
#define STAGE_BYTES 98304
#define OFF_AHI 0
#define OFF_ALO 16384
#define OFF_BHI 32768
#define OFF_BLO 65536
#define SMEM_TOTAL (NSTAGE * STAGE_BYTES)   // 196608

// ---------------- helpers ----------------
static __device__ __forceinline__ void cpa16(uint32_t dst, const void* src) {
    asm volatile("cp.async.cg.shared.global [%0], [%1], 16;\n" :: "r"(dst), "l"(src));
}
static __device__ __forceinline__ void cp_commit() {
    asm volatile("cp.async.commit_group;\n" ::: "memory");
}

static __device__ __forceinline__ void ldsm4(uint32_t (&r)[4], uint32_t addr) {
    asm volatile("ldmatrix.sync.aligned.m8n8.x4.shared.b16 {%0,%1,%2,%3}, [%4];"
                 : "=r"(r[0]), "=r"(r[1]), "=r"(r[2]), "=r"(r[3]) : "r"(addr));
}

static __device__ __forceinline__ void mma16816(float (&d)[4], const uint32_t (&a)[4],
                                                uint32_t b0, uint32_t b1) {
    asm volatile("mma.sync.aligned.m16n8k16.row.col.f32.bf16.bf16.f32 "
                 "{%0,%1,%2,%3}, {%4,%5,%6,%7}, {%8,%9}, {%0,%1,%2,%3};"
                 : "+f"(d[0]), "+f"(d[1]), "+f"(d[2]), "+f"(d[3])
                 : "r"(a[0]), "r"(a[1]), "r"(a[2]), "r"(a[3]), "r"(b0), "r"(b1));
}

// ---------------- kernel 0: fp32 -> (bf16 hi, bf16 lo) ----------------
__global__ void __launch_bounds__(256)
convert_kernel(const float* __restrict__ src, int which, int n4) {
    int i = blockIdx.x * blockDim.x + threadIdx.x;
    if (i >= n4) return;
    __nv_bfloat16* hi = which ? g_Bhi : g_Ahi;
    __nv_bfloat16* lo = which ? g_Blo : g_Alo;
    float4 v = reinterpret_cast<const float4*>(src)[i];
    float f[4] = {v.x, v.y, v.z, v.w};
    __nv_bfloat162 h2[2], l2[2];
    #pragma unroll
    for (int k = 0; k < 4; k++) {
        __nv_bfloat16 h = __float2bfloat16(f[k]);
        __nv_bfloat16 l = __float2bfloat16(f[k] - __bfloat162float(h));
        if (k & 1) { h2[k >> 1].y = h; l2[k >> 1].y = l; }
        else       { h2[k >> 1].x = h; l2[k >> 1].x = l; }
    }
    reinterpret_cast<__nv_bfloat162*>(hi)[i * 2 + 0] = h2[0];
    reinterpret_cast<__nv_bfloat162*>(hi)[i * 2 + 1] = h2[1];
    reinterpret_cast<__nv_bfloat162*>(lo)[i * 2 + 0] = l2[0];
    reinterpret_cast<__nv_bfloat162*>(lo)[i * 2 + 1] = l2[1];
}

// ---------------- stage loader: 6144 x 16B cp.async, swizzled ----------------
// Ahi 1024 chunks | Alo 1024 | Bhi 2048 | Blo 2048 ; 24 per thread
static __device__ __forceinline__ void load_stage(
    uint32_t stb,
    const __nv_bfloat16* __restrict__ pAhi, const __nv_bfloat16* __restrict__ pAlo,
    const __nv_bfloat16* __restrict__ pBhi, const __nv_bfloat16* __restrict__ pBlo,
    int tid)
{
    #pragma unroll
    for (int i = 0; i < 24; i++) {
        const int idx = i * 256 + tid;        // 0..6143
        const __nv_bfloat16* gp;
        uint32_t toff;
        int rem;
        if (idx < 1024)      { rem = idx;        gp = pAhi; toff = OFF_AHI; }
        else if (idx < 2048) { rem = idx - 1024; gp = pAlo; toff = OFF_ALO; }
        else if (idx < 4096) { rem = idx - 2048; gp = pBhi; toff = OFF_BHI; }
        else                 { rem = idx - 4096; gp = pBlo; toff = OFF_BLO; }
        const int row = rem >> 3, c = rem & 7;
        cpa16(stb + toff + (uint32_t)(row * 128 + ((c ^ (row & 7)) << 4)),
              gp + (size_t)row * K2 + c * 8);
    }
    cp_commit();
}

// ---------------- kernel 1: split-K GEMM via mma.sync bf16x3, 64x64 warp tile ----
__global__ void __launch_bounds__(256, 1)
gemm_mma_kernel()
{
    extern __shared__ char smem[];
    const uint32_t sb = (uint32_t)__cvta_generic_to_shared(smem);
    const int tid  = threadIdx.x;
    const int lane = tid & 31;
    const int wid  = tid >> 5;
    const int wm   = (wid >> 2) * 64;    // 2 row bands
    const int wn   = (wid & 3) * 64;     // 4 col bands
    const int bm = blockIdx.x, bn = blockIdx.y, s = blockIdx.z;

    const size_t kbase = (size_t)s * KS;
    const __nv_bfloat16* pAhi = g_Ahi + (size_t)(bm * BM) * K2 + kbase;
    const __nv_bfloat16* pAlo = g_Alo + (size_t)(bm * BM) * K2 + kbase;
    const __nv_bfloat16* pBhi = g_Bhi + (size_t)(bn * BN) * K2 + kbase;
    const __nv_bfloat16* pBlo = g_Blo + (size_t)(bn * BN) * K2 + kbase;

    float acc[4][8][4];
    #pragma unroll
    for (int f = 0; f < 4; f++)
        #pragma unroll
        for (int j = 0; j < 8; j++)
            #pragma unroll
            for (int r = 0; r < 4; r++) acc[f][j][r] = 0.0f;

    // prologue: both stages
    load_stage(sb,               pAhi,      pAlo,      pBhi,      pBlo,      tid);
    load_stage(sb + STAGE_BYTES, pAhi + BK, pAlo + BK, pBhi + BK, pBlo + BK, tid);

    const int lr = lane & 15;     // ldmatrix row within 16
    const int lc = lane >> 4;     // ldmatrix k-half

    for (int it = 0; it < NIT; ++it) {
        // groups committed so far: it+2 ; need group it done -> allow 1 pending
        asm volatile("cp.async.wait_group 1;\n" ::: "memory");
        __syncthreads();

        const uint32_t stb = sb + (uint32_t)(it & 1) * STAGE_BYTES;

        #pragma unroll
        for (int kk = 0; kk < 4; kk++) {          // 4 x k16 per stage
            const int c = kk * 2 + lc;
            // ---- hi fragments ----
            uint32_t aHi[4][4], bHi[4][4];
            #pragma unroll
            for (int f = 0; f < 4; f++) {
                const int row = wm + f * 16 + lr;
                ldsm4(aHi[f], stb + OFF_AHI + (uint32_t)(row * 128 + ((c ^ (row & 7)) << 4)));
            }
            #pragma unroll
            for (int g = 0; g < 4; g++) {
                const int row = wn + g * 16 + lr;
                ldsm4(bHi[g], stb + OFF_BHI + (uint32_t)(row * 128 + ((c ^ (row & 7)) << 4)));
            }
            // pass 1: Ahi * Bhi
            #pragma unroll
            for (int f = 0; f < 4; f++)
                #pragma unroll
                for (int j = 0; j < 8; j++)
                    mma16816(acc[f][j], aHi[f], bHi[j >> 1][j & 1], bHi[j >> 1][(j & 1) + 2]);
            // ---- lo fragments (overlap with pass-1 HMMA issue) ----
            uint32_t aLo[4][4], bLo[4][4];
            #pragma unroll
            for (int f = 0; f < 4; f++) {
                const int row = wm + f * 16 + lr;
                ldsm4(aLo[f], stb + OFF_ALO + (uint32_t)(row * 128 + ((c ^ (row & 7)) << 4)));
            }
            #pragma unroll
            for (int g = 0; g < 4; g++) {
                const int row = wn + g * 16 + lr;
                ldsm4(bLo[g], stb + OFF_BLO + (uint32_t)(row * 128 + ((c ^ (row & 7)) << 4)));
            }
            // pass 2: Ahi * Blo
            #pragma unroll
            for (int f = 0; f < 4; f++)
                #pragma unroll
                for (int j = 0; j < 8; j++)
                    mma16816(acc[f][j], aHi[f], bLo[j >> 1][j & 1], bLo[j >> 1][(j & 1) + 2]);
            // pass 3: Alo * Bhi
            #pragma unroll
            for (int f = 0; f < 4; f++)
                #pragma unroll
                for (int j = 0; j < 8; j++)
                    mma16816(acc[f][j], aLo[f], bHi[j >> 1][j & 1], bHi[j >> 1][(j & 1) + 2]);
        }
        __syncthreads();   // all warps done with this buffer
        if (it + 2 < NIT) {
            const size_t ko = (size_t)(it + 2) * BK;
            load_stage(stb, pAhi + ko, pAlo + ko, pBhi + ko, pBlo + ko, tid);
        } else {
            cp_commit();   // keep group accounting uniform
        }
    }

    // store partials: [s][m][n]
    float* base = g_part + ((size_t)s * MTOT + (size_t)bm * BM) * NTOT + bn * BN;
    #pragma unroll
    for (int f = 0; f < 4; f++) {
        const int r0 = wm + f * 16 + (lane >> 2);
        #pragma unroll
        for (int j = 0; j < 8; j++) {
            const int n0 = wn + j * 8 + (lane & 3) * 2;
            *reinterpret_cast<float2*>(&base[(size_t)r0 * NTOT + n0]) =
                make_float2(acc[f][j][0], acc[f][j][1]);
            *reinterpret_cast<float2*>(&base[(size_t)(r0 + 8) * NTOT + n0]) =
                make_float2(acc[f][j][2], acc[f][j][3]);
        }
    }
}

// ---------------- kernel 2: split-K reduce + bias + einsum ----------------
__global__ void __launch_bounds__(256)
epilogue_kernel(const float* __restrict__ x_all,   // output [64][12][1024][64]
                const float* __restrict__ b_hyp,   // [768]
                float* __restrict__ out)           // [64][12][1024]
{
    __shared__ float sh_h[HORIZON * 65];
    __shared__ float sh_x[BATCH * 65];

    const int n   = blockIdx.x;   // node (m index of GEMM)
    const int tid = threadIdx.x;

    #pragma unroll
    for (int r = 0; r < 3; r++) {
        const int j = tid + 256 * r;              // 0..767
        float acc = b_hyp[j];
        #pragma unroll
        for (int sp = 0; sp < SPLITK; sp++)
            acc += g_part[((size_t)sp * MTOT + n) * NTOT + j];
        sh_h[(j >> 6) * 65 + (j & 63)] = acc;
    }

    #pragma unroll
    for (int r = 0; r < 16; r++) {
        const int i = tid + 256 * r;              // 0..4095
        const int b = i >> 6, f = i & 63;
        sh_x[b * 65 + f] =
            x_all[((size_t)(b * T_IN + (T_IN - 1)) * MTOT + n) * 64 + f];
    }
    __syncthreads();

    #pragma unroll
    for (int r = 0; r < 3; r++) {
        const int j = tid + 256 * r;
        const int b = j / 12, t = j % 12;
        float acc = 0.0f;
        #pragma unroll
        for (int f = 0; f < 64; f++)
            acc += sh_x[b * 65 + f] * sh_h[t * 65 + f];
        out[(size_t)(b * HORIZON + t) * MTOT + n] = acc;
    }
}

// ---------------- launch ----------------
extern "C" void kernel_launch(void* const* d_in, const int* in_sizes, int n_in,
                              void* d_out, int out_size) {
    const float* output  = (const float*)d_in[0];   // [64,12,1024,64]
    const float* weights = (const float*)d_in[1];   // [1024,36864]
    const float* W_hyp   = (const float*)d_in[2];   // [768,36864]
    const float* b_hyp   = (const float*)d_in[3];   // [768]
    float* out = (float*)d_out;

    cudaFuncSetAttribute(gemm_mma_kernel,
                         cudaFuncAttributeMaxDynamicSharedMemorySize, SMEM_TOTAL);

    const int nA4 = MTOT * K2 / 4;
    const int nB4 = NTOT * K2 / 4;
    convert_kernel<<<(nA4 + 255) / 256, 256>>>(weights, 0, nA4);
    convert_kernel<<<(nB4 + 255) / 256, 256>>>(W_hyp,   1, nB4);

    dim3 grid(MTOT / BM, NTOT / BN, SPLITK);   // (8, 3, 6) = 144 CTAs
    gemm_mma_kernel<<<grid, 256, SMEM_TOTAL>>>();

    epilogue_kernel<<<MTOT, 256>>>(output, b_hyp, out);
}

// round 5
// speedup vs baseline: 1.4535x; 1.4535x over previous
#include <cuda_runtime.h>
#include <cuda_fp16.h>
#include <cstdint>

// ---------------- problem constants ----------------
#define K2     36864
#define MTOT   1024
#define NTOT   768
#define SPLITK 6
#define KS     (K2 / SPLITK)      // 6144 k per CTA
#define BM     128
#define BN     256
#define BK     64                 // fp16 k per pipeline stage (128B rows)
#define NIT    (KS / BK)          // 96
#define NSTAGE 2

#define BATCH   64
#define T_IN    12
#define HORIZON 12

// ---------------- device scratch ----------------
__device__ __half g_Ah [(size_t)MTOT * K2];   // A rounded once to fp16
__device__ __half g_Bhi[(size_t)NTOT * K2];   // B hi
__device__ __half g_Blo[(size_t)NTOT * K2];   // B residual
__device__ float  g_part[(size_t)SPLITK * MTOT * NTOT];   // [s][m][n]

// ---------------- SMEM layout ----------------
// per stage: A 16K | Bhi 32K | Blo 32K = 80K; 2 stages = 160K
#define OFF_A   0
#define OFF_BHI 16384
#define OFF_BLO 49152
#define STAGE_BYTES 81920
#define SMEM_TOTAL (NSTAGE * STAGE_BYTES)   // 163840

// ---------------- helpers ----------------
static __device__ __forceinline__ void cpa16(uint32_t dst, const void* src) {
    asm volatile("cp.async.cg.shared.global [%0], [%1], 16;\n" :: "r"(dst), "l"(src));
}
static __device__ __forceinline__ void cp_commit() {
    asm volatile("cp.async.commit_group;\n" ::: "memory");
}

static __device__ __forceinline__ void ldsm4(uint32_t (&r)[4], uint32_t addr) {
    asm volatile("ldmatrix.sync.aligned.m8n8.x4.shared.b16 {%0,%1,%2,%3}, [%4];"
                 : "=r"(r[0]), "=r"(r[1]), "=r"(r[2]), "=r"(r[3]) : "r"(addr));
}

static __device__ __forceinline__ void mma16816(float (&d)[4], const uint32_t (&a)[4],
                                                uint32_t b0, uint32_t b1) {
    asm volatile("mma.sync.aligned.m16n8k16.row.col.f32.f16.f16.f32 "
                 "{%0,%1,%2,%3}, {%4,%5,%6,%7}, {%8,%9}, {%0,%1,%2,%3};"
                 : "+f"(d[0]), "+f"(d[1]), "+f"(d[2]), "+f"(d[3])
                 : "r"(a[0]), "r"(a[1]), "r"(a[2]), "r"(a[3]), "r"(b0), "r"(b1));
}

// ---------------- kernel 0a: A fp32 -> fp16 (single rounding) ----------------
__global__ void __launch_bounds__(256)
convertA_kernel(const float* __restrict__ src, int n4) {
    int i = blockIdx.x * blockDim.x + threadIdx.x;
    if (i >= n4) return;
    float4 v = reinterpret_cast<const float4*>(src)[i];
    __half2 h0 = make_half2(__float2half(v.x), __float2half(v.y));
    __half2 h1 = make_half2(__float2half(v.z), __float2half(v.w));
    reinterpret_cast<__half2*>(g_Ah)[i * 2 + 0] = h0;
    reinterpret_cast<__half2*>(g_Ah)[i * 2 + 1] = h1;
}

// ---------------- kernel 0b: B fp32 -> (fp16 hi, fp16 lo) ----------------
__global__ void __launch_bounds__(256)
convertB_kernel(const float* __restrict__ src, int n4) {
    int i = blockIdx.x * blockDim.x + threadIdx.x;
    if (i >= n4) return;
    float4 v = reinterpret_cast<const float4*>(src)[i];
    float f[4] = {v.x, v.y, v.z, v.w};
    __half h[4], l[4];
    #pragma unroll
    for (int k = 0; k < 4; k++) {
        h[k] = __float2half(f[k]);
        l[k] = __float2half(f[k] - __half2float(h[k]));
    }
    reinterpret_cast<__half2*>(g_Bhi)[i * 2 + 0] = make_half2(h[0], h[1]);
    reinterpret_cast<__half2*>(g_Bhi)[i * 2 + 1] = make_half2(h[2], h[3]);
    reinterpret_cast<__half2*>(g_Blo)[i * 2 + 0] = make_half2(l[0], l[1]);
    reinterpret_cast<__half2*>(g_Blo)[i * 2 + 1] = make_half2(l[2], l[3]);
}

// ---------------- stage loader: 5120 x 16B cp.async, swizzled ----------------
// A 1024 chunks | Bhi 2048 | Blo 2048 ; 20 per thread
static __device__ __forceinline__ void load_stage(
    uint32_t stb,
    const __half* __restrict__ pA,
    const __half* __restrict__ pBhi, const __half* __restrict__ pBlo,
    int tid)
{
    #pragma unroll
    for (int i = 0; i < 20; i++) {
        const int idx = i * 256 + tid;        // 0..5119
        const __half* gp;
        uint32_t toff;
        int rem;
        if (idx < 1024)      { rem = idx;        gp = pA;   toff = OFF_A;   }
        else if (idx < 3072) { rem = idx - 1024; gp = pBhi; toff = OFF_BHI; }
        else                 { rem = idx - 3072; gp = pBlo; toff = OFF_BLO; }
        const int row = rem >> 3, c = rem & 7;
        cpa16(stb + toff + (uint32_t)(row * 128 + ((c ^ (row & 7)) << 4)),
              gp + (size_t)row * K2 + c * 8);
    }
    cp_commit();
}

// ---------------- kernel 1: split-K GEMM, fp16 2-pass, 64x64 warp tile ------
__global__ void __launch_bounds__(256, 1)
gemm_mma_kernel()
{
    extern __shared__ char smem[];
    const uint32_t sb = (uint32_t)__cvta_generic_to_shared(smem);
    const int tid  = threadIdx.x;
    const int lane = tid & 31;
    const int wid  = tid >> 5;
    const int wm   = (wid >> 2) * 64;    // 2 row bands
    const int wn   = (wid & 3) * 64;     // 4 col bands
    const int bm = blockIdx.x, bn = blockIdx.y, s = blockIdx.z;

    const size_t kbase = (size_t)s * KS;
    const __half* pA   = g_Ah  + (size_t)(bm * BM) * K2 + kbase;
    const __half* pBhi = g_Bhi + (size_t)(bn * BN) * K2 + kbase;
    const __half* pBlo = g_Blo + (size_t)(bn * BN) * K2 + kbase;

    float acc[4][8][4];
    #pragma unroll
    for (int f = 0; f < 4; f++)
        #pragma unroll
        for (int j = 0; j < 8; j++)
            #pragma unroll
            for (int r = 0; r < 4; r++) acc[f][j][r] = 0.0f;

    // prologue: both stages
    load_stage(sb,               pA,      pBhi,      pBlo,      tid);
    load_stage(sb + STAGE_BYTES, pA + BK, pBhi + BK, pBlo + BK, tid);

    const int lr = lane & 15;     // ldmatrix row within 16
    const int lc = lane >> 4;     // ldmatrix k-half

    for (int it = 0; it < NIT; ++it) {
        asm volatile("cp.async.wait_group 1;\n" ::: "memory");
        __syncthreads();

        const uint32_t stb = sb + (uint32_t)(it & 1) * STAGE_BYTES;

        #pragma unroll
        for (int kk = 0; kk < 4; kk++) {          // 4 x k16 per stage
            const int c = kk * 2 + lc;
            uint32_t aH[4][4], bHi[4][4], bLo[4][4];
            #pragma unroll
            for (int f = 0; f < 4; f++) {
                const int row = wm + f * 16 + lr;
                ldsm4(aH[f], stb + OFF_A + (uint32_t)(row * 128 + ((c ^ (row & 7)) << 4)));
            }
            #pragma unroll
            for (int g = 0; g < 4; g++) {
                const int row = wn + g * 16 + lr;
                const uint32_t off = (uint32_t)(row * 128 + ((c ^ (row & 7)) << 4));
                ldsm4(bHi[g], stb + OFF_BHI + off);
                ldsm4(bLo[g], stb + OFF_BLO + off);
            }
            // pass 1: A * Bhi
            #pragma unroll
            for (int f = 0; f < 4; f++)
                #pragma unroll
                for (int j = 0; j < 8; j++)
                    mma16816(acc[f][j], aH[f], bHi[j >> 1][j & 1], bHi[j >> 1][(j & 1) + 2]);
            // pass 2: A * Blo
            #pragma unroll
            for (int f = 0; f < 4; f++)
                #pragma unroll
                for (int j = 0; j < 8; j++)
                    mma16816(acc[f][j], aH[f], bLo[j >> 1][j & 1], bLo[j >> 1][(j & 1) + 2]);
        }
        __syncthreads();   // all warps done with this buffer
        if (it + 2 < NIT) {
            const size_t ko = (size_t)(it + 2) * BK;
            load_stage(stb, pA + ko, pBhi + ko, pBlo + ko, tid);
        } else {
            cp_commit();   // keep group accounting uniform
        }
    }

    // store partials: [s][m][n]
    float* base = g_part + ((size_t)s * MTOT + (size_t)bm * BM) * NTOT + bn * BN;
    #pragma unroll
    for (int f = 0; f < 4; f++) {
        const int r0 = wm + f * 16 + (lane >> 2);
        #pragma unroll
        for (int j = 0; j < 8; j++) {
            const int n0 = wn + j * 8 + (lane & 3) * 2;
            *reinterpret_cast<float2*>(&base[(size_t)r0 * NTOT + n0]) =
                make_float2(acc[f][j][0], acc[f][j][1]);
            *reinterpret_cast<float2*>(&base[(size_t)(r0 + 8) * NTOT + n0]) =
                make_float2(acc[f][j][2], acc[f][j][3]);
        }
    }
}

// ---------------- kernel 2: split-K reduce + bias + einsum ----------------
__global__ void __launch_bounds__(256)
epilogue_kernel(const float* __restrict__ x_all,   // output [64][12][1024][64]
                const float* __restrict__ b_hyp,   // [768]
                float* __restrict__ out)           // [64][12][1024]
{
    __shared__ float sh_h[HORIZON * 65];
    __shared__ float sh_x[BATCH * 65];

    const int n   = blockIdx.x;   // node (m index of GEMM)
    const int tid = threadIdx.x;

    #pragma unroll
    for (int r = 0; r < 3; r++) {
        const int j = tid + 256 * r;              // 0..767
        float acc = b_hyp[j];
        #pragma unroll
        for (int sp = 0; sp < SPLITK; sp++)
            acc += g_part[((size_t)sp * MTOT + n) * NTOT + j];
        sh_h[(j >> 6) * 65 + (j & 63)] = acc;
    }

    #pragma unroll
    for (int r = 0; r < 16; r++) {
        const int i = tid + 256 * r;              // 0..4095
        const int b = i >> 6, f = i & 63;
        sh_x[b * 65 + f] =
            x_all[((size_t)(b * T_IN + (T_IN - 1)) * MTOT + n) * 64 + f];
    }
    __syncthreads();

    #pragma unroll
    for (int r = 0; r < 3; r++) {
        const int j = tid + 256 * r;
        const int b = j / 12, t = j % 12;
        float acc = 0.0f;
        #pragma unroll
        for (int f = 0; f < 64; f++)
            acc += sh_x[b * 65 + f] * sh_h[t * 65 + f];
        out[(size_t)(b * HORIZON + t) * MTOT + n] = acc;
    }
}

// ---------------- launch ----------------
extern "C" void kernel_launch(void* const* d_in, const int* in_sizes, int n_in,
                              void* d_out, int out_size) {
    const float* output  = (const float*)d_in[0];   // [64,12,1024,64]
    const float* weights = (const float*)d_in[1];   // [1024,36864]
    const float* W_hyp   = (const float*)d_in[2];   // [768,36864]
    const float* b_hyp   = (const float*)d_in[3];   // [768]
    float* out = (float*)d_out;

    cudaFuncSetAttribute(gemm_mma_kernel,
                         cudaFuncAttributeMaxDynamicSharedMemorySize, SMEM_TOTAL);

    const int nA4 = MTOT * K2 / 4;
    const int nB4 = NTOT * K2 / 4;
    convertA_kernel<<<(nA4 + 255) / 256, 256>>>(weights, nA4);
    convertB_kernel<<<(nB4 + 255) / 256, 256>>>(W_hyp,   nB4);

    dim3 grid(MTOT / BM, NTOT / BN, SPLITK);   // (8, 3, 6) = 144 CTAs
    gemm_mma_kernel<<<grid, 256, SMEM_TOTAL>>>();

    epilogue_kernel<<<MTOT, 256>>>(output, b_hyp, out);
}

// round 6
// speedup vs baseline: 2.2258x; 1.5313x over previous
#include <cuda_runtime.h>
#include <cuda_fp16.h>
#include <cstdint>

// ---------------- problem constants ----------------
#define K2     36864
#define MTOT   1024
#define NTOT   768
#define SPLITK 6
#define KS     (K2 / SPLITK)      // 6144 k per CTA
#define BM     128
#define BN     256
#define BK     64                 // fp16 k per pipeline stage (128B rows)
#define NIT    (KS / BK)          // 96
#define NSTAGE 3

#define BATCH   64
#define T_IN    12
#define HORIZON 12

// ---------------- device scratch ----------------
__device__ __half g_Ah[(size_t)MTOT * K2];   // A rounded once to fp16
__device__ __half g_Bh[(size_t)NTOT * K2];   // B rounded once to fp16
__device__ float  g_part[(size_t)SPLITK * MTOT * NTOT];   // [s][m][n]

// ---------------- SMEM layout ----------------
// per stage: A 16K | B 32K = 48K; 3 stages = 144K
#define OFF_A   0
#define OFF_B   16384
#define STAGE_BYTES 49152
#define SMEM_TOTAL (NSTAGE * STAGE_BYTES)   // 147456

// ---------------- helpers ----------------
static __device__ __forceinline__ void cpa16(uint32_t dst, const void* src) {
    asm volatile("cp.async.cg.shared.global [%0], [%1], 16;\n" :: "r"(dst), "l"(src));
}
static __device__ __forceinline__ void cp_commit() {
    asm volatile("cp.async.commit_group;\n" ::: "memory");
}

static __device__ __forceinline__ void ldsm4(uint32_t (&r)[4], uint32_t addr) {
    asm volatile("ldmatrix.sync.aligned.m8n8.x4.shared.b16 {%0,%1,%2,%3}, [%4];"
                 : "=r"(r[0]), "=r"(r[1]), "=r"(r[2]), "=r"(r[3]) : "r"(addr));
}

static __device__ __forceinline__ void mma16816(float (&d)[4], const uint32_t (&a)[4],
                                                uint32_t b0, uint32_t b1) {
    asm volatile("mma.sync.aligned.m16n8k16.row.col.f32.f16.f16.f32 "
                 "{%0,%1,%2,%3}, {%4,%5,%6,%7}, {%8,%9}, {%0,%1,%2,%3};"
                 : "+f"(d[0]), "+f"(d[1]), "+f"(d[2]), "+f"(d[3])
                 : "r"(a[0]), "r"(a[1]), "r"(a[2]), "r"(a[3]), "r"(b0), "r"(b1));
}

// ---------------- kernel 0: fp32 -> fp16 (single rounding) ----------------
__global__ void __launch_bounds__(256)
convert_kernel(const float* __restrict__ src, int which, int n4) {
    int i = blockIdx.x * blockDim.x + threadIdx.x;
    if (i >= n4) return;
    __half* dst = which ? g_Bh : g_Ah;
    float4 v = reinterpret_cast<const float4*>(src)[i];
    reinterpret_cast<__half2*>(dst)[i * 2 + 0] =
        make_half2(__float2half(v.x), __float2half(v.y));
    reinterpret_cast<__half2*>(dst)[i * 2 + 1] =
        make_half2(__float2half(v.z), __float2half(v.w));
}

// ---------------- stage loader: 3072 x 16B cp.async, swizzled ----------------
// A 1024 chunks | B 2048 chunks ; 12 per thread
static __device__ __forceinline__ void load_stage(
    uint32_t stb,
    const __half* __restrict__ pA, const __half* __restrict__ pB,
    int tid)
{
    #pragma unroll
    for (int i = 0; i < 12; i++) {
        const int idx = i * 256 + tid;        // 0..3071
        const __half* gp;
        uint32_t toff;
        int rem;
        if (idx < 1024) { rem = idx;        gp = pA; toff = OFF_A; }
        else            { rem = idx - 1024; gp = pB; toff = OFF_B; }
        const int row = rem >> 3, c = rem & 7;
        cpa16(stb + toff + (uint32_t)(row * 128 + ((c ^ (row & 7)) << 4)),
              gp + (size_t)row * K2 + c * 8);
    }
    cp_commit();
}

// ---------------- kernel 1: split-K GEMM, fp16 single pass, 64x64 warp tile --
__global__ void __launch_bounds__(256, 1)
gemm_mma_kernel()
{
    extern __shared__ char smem[];
    const uint32_t sb = (uint32_t)__cvta_generic_to_shared(smem);
    const int tid  = threadIdx.x;
    const int lane = tid & 31;
    const int wid  = tid >> 5;
    const int wm   = (wid >> 2) * 64;    // 2 row bands
    const int wn   = (wid & 3) * 64;     // 4 col bands
    const int bm = blockIdx.x, bn = blockIdx.y, s = blockIdx.z;

    const size_t kbase = (size_t)s * KS;
    const __half* pA = g_Ah + (size_t)(bm * BM) * K2 + kbase;
    const __half* pB = g_Bh + (size_t)(bn * BN) * K2 + kbase;

    float acc[4][8][4];
    #pragma unroll
    for (int f = 0; f < 4; f++)
        #pragma unroll
        for (int j = 0; j < 8; j++)
            #pragma unroll
            for (int r = 0; r < 4; r++) acc[f][j][r] = 0.0f;

    // prologue: fill all three stages
    load_stage(sb,                   pA,          pB,          tid);
    load_stage(sb + STAGE_BYTES,     pA + BK,     pB + BK,     tid);
    load_stage(sb + 2 * STAGE_BYTES, pA + 2 * BK, pB + 2 * BK, tid);

    const int lr = lane & 15;     // ldmatrix row within 16
    const int lc = lane >> 4;     // ldmatrix k-half

    for (int it = 0; it < NIT; ++it) {
        // committed groups so far: it + 3 ; allow 2 pending -> stage it complete
        asm volatile("cp.async.wait_group 2;\n" ::: "memory");
        __syncthreads();

        const uint32_t stb = sb + (uint32_t)(it % NSTAGE) * STAGE_BYTES;

        #pragma unroll
        for (int kk = 0; kk < 4; kk++) {          // 4 x k16 per stage
            const int c = kk * 2 + lc;
            uint32_t aH[4][4], bH[4][4];
            #pragma unroll
            for (int f = 0; f < 4; f++) {
                const int row = wm + f * 16 + lr;
                ldsm4(aH[f], stb + OFF_A + (uint32_t)(row * 128 + ((c ^ (row & 7)) << 4)));
            }
            #pragma unroll
            for (int g = 0; g < 4; g++) {
                const int row = wn + g * 16 + lr;
                ldsm4(bH[g], stb + OFF_B + (uint32_t)(row * 128 + ((c ^ (row & 7)) << 4)));
            }
            #pragma unroll
            for (int f = 0; f < 4; f++)
                #pragma unroll
                for (int j = 0; j < 8; j++)
                    mma16816(acc[f][j], aH[f], bH[j >> 1][j & 1], bH[j >> 1][(j & 1) + 2]);
        }
        __syncthreads();   // all warps done with this buffer
        if (it + NSTAGE < NIT) {
            const size_t ko = (size_t)(it + NSTAGE) * BK;
            load_stage(stb, pA + ko, pB + ko, tid);
        } else {
            cp_commit();   // keep group accounting uniform
        }
    }

    // store partials: [s][m][n]
    float* base = g_part + ((size_t)s * MTOT + (size_t)bm * BM) * NTOT + bn * BN;
    #pragma unroll
    for (int f = 0; f < 4; f++) {
        const int r0 = wm + f * 16 + (lane >> 2);
        #pragma unroll
        for (int j = 0; j < 8; j++) {
            const int n0 = wn + j * 8 + (lane & 3) * 2;
            *reinterpret_cast<float2*>(&base[(size_t)r0 * NTOT + n0]) =
                make_float2(acc[f][j][0], acc[f][j][1]);
            *reinterpret_cast<float2*>(&base[(size_t)(r0 + 8) * NTOT + n0]) =
                make_float2(acc[f][j][2], acc[f][j][3]);
        }
    }
}

// ---------------- kernel 2: split-K reduce + bias + einsum ----------------
__global__ void __launch_bounds__(256)
epilogue_kernel(const float* __restrict__ x_all,   // output [64][12][1024][64]
                const float* __restrict__ b_hyp,   // [768]
                float* __restrict__ out)           // [64][12][1024]
{
    __shared__ float sh_h[HORIZON * 65];
    __shared__ float sh_x[BATCH * 65];

    const int n   = blockIdx.x;   // node (m index of GEMM)
    const int tid = threadIdx.x;

    #pragma unroll
    for (int r = 0; r < 3; r++) {
        const int j = tid + 256 * r;              // 0..767
        float acc = b_hyp[j];
        #pragma unroll
        for (int sp = 0; sp < SPLITK; sp++)
            acc += g_part[((size_t)sp * MTOT + n) * NTOT + j];
        sh_h[(j >> 6) * 65 + (j & 63)] = acc;
    }

    #pragma unroll
    for (int r = 0; r < 16; r++) {
        const int i = tid + 256 * r;              // 0..4095
        const int b = i >> 6, f = i & 63;
        sh_x[b * 65 + f] =
            x_all[((size_t)(b * T_IN + (T_IN - 1)) * MTOT + n) * 64 + f];
    }
    __syncthreads();

    #pragma unroll
    for (int r = 0; r < 3; r++) {
        const int j = tid + 256 * r;
        const int b = j / 12, t = j % 12;
        float acc = 0.0f;
        #pragma unroll
        for (int f = 0; f < 64; f++)
            acc += sh_x[b * 65 + f] * sh_h[t * 65 + f];
        out[(size_t)(b * HORIZON + t) * MTOT + n] = acc;
    }
}

// ---------------- launch ----------------
extern "C" void kernel_launch(void* const* d_in, const int* in_sizes, int n_in,
                              void* d_out, int out_size) {
    const float* output  = (const float*)d_in[0];   // [64,12,1024,64]
    const float* weights = (const float*)d_in[1];   // [1024,36864]
    const float* W_hyp   = (const float*)d_in[2];   // [768,36864]
    const float* b_hyp   = (const float*)d_in[3];   // [768]
    float* out = (float*)d_out;

    cudaFuncSetAttribute(gemm_mma_kernel,
                         cudaFuncAttributeMaxDynamicSharedMemorySize, SMEM_TOTAL);

    const int nA4 = MTOT * K2 / 4;
    const int nB4 = NTOT * K2 / 4;
    convert_kernel<<<(nA4 + 255) / 256, 256>>>(weights, 0, nA4);
    convert_kernel<<<(nB4 + 255) / 256, 256>>>(W_hyp,   1, nB4);

    dim3 grid(MTOT / BM, NTOT / BN, SPLITK);   // (8, 3, 6) = 144 CTAs
    gemm_mma_kernel<<<grid, 256, SMEM_TOTAL>>>();

    epilogue_kernel<<<MTOT, 256>>>(output, b_hyp, out);
}

// round 7
// speedup vs baseline: 2.5251x; 1.1345x over previous
#include <cuda_runtime.h>
#include <cuda_fp16.h>
#include <cstdint>

// ---------------- problem constants ----------------
#define K2     36864
#define MTOT   1024
#define NTOT   768
#define SPLITK 6
#define KS     (K2 / SPLITK)      // 6144 k per CTA
#define BM     128
#define BN     256
#define BK     64                 // fp16 k per pipeline stage (128B rows)
#define NIT    (KS / BK)          // 96
#define NSTAGE 3

#define BATCH   64
#define T_IN    12
#define HORIZON 12

// ---------------- device scratch ----------------
__device__ __half g_Bh[(size_t)NTOT * K2];                 // B rounded once to fp16
__device__ float  g_part[(size_t)SPLITK * MTOT * NTOT];    // [s][m][n]

// ---------------- SMEM layout ----------------
// per stage: A 16K | B 32K = 48K; 3 stages = 144K
#define OFF_A   0
#define OFF_B   16384
#define STAGE_BYTES 49152
#define SMEM_TOTAL (NSTAGE * STAGE_BYTES)   // 147456

// ---------------- helpers ----------------
static __device__ __forceinline__ void cpa16(uint32_t dst, const void* src) {
    asm volatile("cp.async.cg.shared.global [%0], [%1], 16;\n" :: "r"(dst), "l"(src));
}
static __device__ __forceinline__ void cp_commit() {
    asm volatile("cp.async.commit_group;\n" ::: "memory");
}

static __device__ __forceinline__ void ldsm4(uint32_t (&r)[4], uint32_t addr) {
    asm volatile("ldmatrix.sync.aligned.m8n8.x4.shared.b16 {%0,%1,%2,%3}, [%4];"
                 : "=r"(r[0]), "=r"(r[1]), "=r"(r[2]), "=r"(r[3]) : "r"(addr));
}

static __device__ __forceinline__ void mma16816(float (&d)[4], const uint32_t (&a)[4],
                                                uint32_t b0, uint32_t b1) {
    asm volatile("mma.sync.aligned.m16n8k16.row.col.f32.f16.f16.f32 "
                 "{%0,%1,%2,%3}, {%4,%5,%6,%7}, {%8,%9}, {%0,%1,%2,%3};"
                 : "+f"(d[0]), "+f"(d[1]), "+f"(d[2]), "+f"(d[3])
                 : "r"(a[0]), "r"(a[1]), "r"(a[2]), "r"(a[3]), "r"(b0), "r"(b1));
}

static __device__ __forceinline__ uint32_t pack_h2(float lo, float hi) {
    uint32_t r;
    asm("cvt.rn.f16x2.f32 %0, %1, %2;" : "=r"(r) : "f"(hi), "f"(lo));
    return r;
}

// ---------------- kernel 0: B fp32 -> fp16 (single rounding, 16B out/thread) --
__global__ void __launch_bounds__(256)
convertB_kernel(const float* __restrict__ src, int n8) {
    int i = blockIdx.x * blockDim.x + threadIdx.x;
    if (i >= n8) return;
    float4 v0 = reinterpret_cast<const float4*>(src)[2 * i];
    float4 v1 = reinterpret_cast<const float4*>(src)[2 * i + 1];
    uint4 o;
    o.x = pack_h2(v0.x, v0.y);
    o.y = pack_h2(v0.z, v0.w);
    o.z = pack_h2(v1.x, v1.y);
    o.w = pack_h2(v1.z, v1.w);
    reinterpret_cast<uint4*>(g_Bh)[i] = o;
}

// ---------------- A loader pieces (fp32 LDG -> regs -> cvt -> STS) ----------
// A per stage: 1024 x 16B fp16 chunks; 4 chunks/thread; each chunk = 2 float4 fp32.
static __device__ __forceinline__ void loadA_regs(float4 (&av)[8],
                                                  const float* __restrict__ pA, int tid) {
    #pragma unroll
    for (int i = 0; i < 4; i++) {
        const int idx = i * 256 + tid;
        const int row = idx >> 3, c = idx & 7;
        const float* src = pA + (size_t)row * K2 + c * 8;
        av[2 * i]     = *reinterpret_cast<const float4*>(src);
        av[2 * i + 1] = *reinterpret_cast<const float4*>(src + 4);
    }
}
static __device__ __forceinline__ void storeA_smem(const float4 (&av)[8],
                                                   uint32_t stb, int tid) {
    #pragma unroll
    for (int i = 0; i < 4; i++) {
        const int idx = i * 256 + tid;
        const int row = idx >> 3, c = idx & 7;
        const uint32_t r0 = pack_h2(av[2 * i].x,     av[2 * i].y);
        const uint32_t r1 = pack_h2(av[2 * i].z,     av[2 * i].w);
        const uint32_t r2 = pack_h2(av[2 * i + 1].x, av[2 * i + 1].y);
        const uint32_t r3 = pack_h2(av[2 * i + 1].z, av[2 * i + 1].w);
        const uint32_t dst = stb + OFF_A + (uint32_t)(row * 128 + ((c ^ (row & 7)) << 4));
        asm volatile("st.shared.v4.b32 [%0], {%1,%2,%3,%4};"
                     :: "r"(dst), "r"(r0), "r"(r1), "r"(r2), "r"(r3));
    }
}

// B per stage: 2048 x 16B chunks via cp.async; 8/thread; one commit group per stage.
static __device__ __forceinline__ void loadB_stage(uint32_t stb,
                                                   const __half* __restrict__ pB, int tid) {
    #pragma unroll
    for (int i = 0; i < 8; i++) {
        const int rem = i * 256 + tid;
        const int row = rem >> 3, c = rem & 7;
        cpa16(stb + OFF_B + (uint32_t)(row * 128 + ((c ^ (row & 7)) << 4)),
              pB + (size_t)row * K2 + c * 8);
    }
    cp_commit();
}

// ---------------- kernel 1: split-K GEMM, fused A convert, 64x64 warp tile ---
__global__ void __launch_bounds__(256, 1)
gemm_mma_kernel(const float* __restrict__ Afp32)
{
    extern __shared__ char smem[];
    const uint32_t sb = (uint32_t)__cvta_generic_to_shared(smem);
    const int tid  = threadIdx.x;
    const int lane = tid & 31;
    const int wid  = tid >> 5;
    const int wm   = (wid >> 2) * 64;    // 2 row bands
    const int wn   = (wid & 3) * 64;     // 4 col bands
    const int bm = blockIdx.x, bn = blockIdx.y, s = blockIdx.z;

    const size_t kbase = (size_t)s * KS;
    const float*  pA = Afp32 + (size_t)(bm * BM) * K2 + kbase;
    const __half* pB = g_Bh  + (size_t)(bn * BN) * K2 + kbase;

    float acc[4][8][4];
    #pragma unroll
    for (int f = 0; f < 4; f++)
        #pragma unroll
        for (int j = 0; j < 8; j++)
            #pragma unroll
            for (int r = 0; r < 4; r++) acc[f][j][r] = 0.0f;

    // prologue: B via cp.async for stages 0..2 (3 ordered commit groups)
    loadB_stage(sb,                   pB,          tid);
    loadB_stage(sb + STAGE_BYTES,     pB + BK,     tid);
    loadB_stage(sb + 2 * STAGE_BYTES, pB + 2 * BK, tid);
    // prologue: A (fp32 -> fp16) for stages 0..2
    {
        float4 av[8];
        loadA_regs(av, pA, tid);          storeA_smem(av, sb, tid);
        loadA_regs(av, pA + BK, tid);     storeA_smem(av, sb + STAGE_BYTES, tid);
        loadA_regs(av, pA + 2 * BK, tid); storeA_smem(av, sb + 2 * STAGE_BYTES, tid);
    }

    const int lr = lane & 15;     // ldmatrix row within 16
    const int lc = lane >> 4;     // ldmatrix k-half

    for (int it = 0; it < NIT; ++it) {
        const bool ld = (it + NSTAGE) < NIT;

        // issue A fp32 loads for stage it+3 early (gmem only; consumed after compute)
        float4 av[8];
        if (ld) loadA_regs(av, pA + (size_t)(it + NSTAGE) * BK, tid);

        // B of stage it complete (3+it groups committed; allow 2 pending)
        asm volatile("cp.async.wait_group 2;\n" ::: "memory");
        __syncthreads();

        const uint32_t stb = sb + (uint32_t)(it % NSTAGE) * STAGE_BYTES;

        #pragma unroll
        for (int kk = 0; kk < 4; kk++) {          // 4 x k16 per stage
            const int c = kk * 2 + lc;
            uint32_t aH[4][4], bH[4][4];
            #pragma unroll
            for (int f = 0; f < 4; f++) {
                const int row = wm + f * 16 + lr;
                ldsm4(aH[f], stb + OFF_A + (uint32_t)(row * 128 + ((c ^ (row & 7)) << 4)));
            }
            #pragma unroll
            for (int g = 0; g < 4; g++) {
                const int row = wn + g * 16 + lr;
                ldsm4(bH[g], stb + OFF_B + (uint32_t)(row * 128 + ((c ^ (row & 7)) << 4)));
            }
            #pragma unroll
            for (int f = 0; f < 4; f++)
                #pragma unroll
                for (int j = 0; j < 8; j++)
                    mma16816(acc[f][j], aH[f], bH[j >> 1][j & 1], bH[j >> 1][(j & 1) + 2]);
        }
        __syncthreads();   // all warps done reading stage it%3

        if (ld) {
            storeA_smem(av, stb, tid);                              // A -> stage it%3
            loadB_stage(stb, pB + (size_t)(it + NSTAGE) * BK, tid); // B -> stage it%3 (1 commit)
        } else {
            cp_commit();   // keep group accounting uniform
        }
    }

    // store partials: [s][m][n]
    float* base = g_part + ((size_t)s * MTOT + (size_t)bm * BM) * NTOT + bn * BN;
    #pragma unroll
    for (int f = 0; f < 4; f++) {
        const int r0 = wm + f * 16 + (lane >> 2);
        #pragma unroll
        for (int j = 0; j < 8; j++) {
            const int n0 = wn + j * 8 + (lane & 3) * 2;
            *reinterpret_cast<float2*>(&base[(size_t)r0 * NTOT + n0]) =
                make_float2(acc[f][j][0], acc[f][j][1]);
            *reinterpret_cast<float2*>(&base[(size_t)(r0 + 8) * NTOT + n0]) =
                make_float2(acc[f][j][2], acc[f][j][3]);
        }
    }
}

// ---------------- kernel 2: split-K reduce + bias + einsum (float4) ---------
__global__ void __launch_bounds__(256)
epilogue_kernel(const float* __restrict__ x_all,   // output [64][12][1024][64]
                const float* __restrict__ b_hyp,   // [768]
                float* __restrict__ out)           // [64][12][1024]
{
    __shared__ float4 sh_h4[HORIZON * 17];   // [t][16] pad 17
    __shared__ float4 sh_x4[BATCH * 17];     // [b][16] pad 17

    const int n   = blockIdx.x;   // node (m index of GEMM)
    const int tid = threadIdx.x;

    // h: 192 float4 (768 floats): split-K reduce + bias
    if (tid < 192) {
        float4 a = reinterpret_cast<const float4*>(b_hyp)[tid];
        #pragma unroll
        for (int sp = 0; sp < SPLITK; sp++) {
            float4 v = *reinterpret_cast<const float4*>(
                &g_part[((size_t)sp * MTOT + n) * NTOT + tid * 4]);
            a.x += v.x; a.y += v.y; a.z += v.z; a.w += v.w;
        }
        sh_h4[(tid >> 4) * 17 + (tid & 15)] = a;
    }

    // x: 1024 float4 (64 b x 16 fc)
    #pragma unroll
    for (int r = 0; r < 4; r++) {
        const int i = tid + 256 * r;          // 0..1023
        const int b = i >> 4, fc = i & 15;
        sh_x4[b * 17 + fc] = *reinterpret_cast<const float4*>(
            &x_all[((size_t)(b * T_IN + (T_IN - 1)) * MTOT + n) * 64 + fc * 4]);
    }
    __syncthreads();

    #pragma unroll
    for (int r = 0; r < 3; r++) {
        const int j = tid + 256 * r;          // 0..767
        const int b = j / 12, t = j % 12;
        float acc = 0.0f;
        #pragma unroll
        for (int fc = 0; fc < 16; fc++) {
            const float4 xv = sh_x4[b * 17 + fc];
            const float4 hv = sh_h4[t * 17 + fc];
            acc += xv.x * hv.x + xv.y * hv.y + xv.z * hv.z + xv.w * hv.w;
        }
        out[(size_t)(b * HORIZON + t) * MTOT + n] = acc;
    }
}

// ---------------- launch ----------------
extern "C" void kernel_launch(void* const* d_in, const int* in_sizes, int n_in,
                              void* d_out, int out_size) {
    const float* output  = (const float*)d_in[0];   // [64,12,1024,64]
    const float* weights = (const float*)d_in[1];   // [1024,36864]
    const float* W_hyp   = (const float*)d_in[2];   // [768,36864]
    const float* b_hyp   = (const float*)d_in[3];   // [768]
    float* out = (float*)d_out;

    cudaFuncSetAttribute(gemm_mma_kernel,
                         cudaFuncAttributeMaxDynamicSharedMemorySize, SMEM_TOTAL);

    const int nB8 = NTOT * K2 / 8;   // 3538944
    convertB_kernel<<<(nB8 + 255) / 256, 256>>>(W_hyp, nB8);

    dim3 grid(MTOT / BM, NTOT / BN, SPLITK);   // (8, 3, 6) = 144 CTAs
    gemm_mma_kernel<<<grid, 256, SMEM_TOTAL>>>(weights);

    epilogue_kernel<<<MTOT, 256>>>(output, b_hyp, out);
}

// round 8
// speedup vs baseline: 2.6202x; 1.0377x over previous
#include <cuda_runtime.h>
#include <cuda_fp16.h>
#include <cstdint>

// ---------------- problem constants ----------------
#define K2     36864
#define MTOT   1024
#define NTOT   768
#define SPLITK 6
#define KS     (K2 / SPLITK)      // 6144 k per CTA
#define BM     128
#define BN     256
#define BK     64                 // fp16 k per pipeline stage (128B rows)
#define NIT    (KS / BK)          // 96
#define NSTAGE 4

#define BATCH   64
#define T_IN    12
#define HORIZON 12

// ---------------- device scratch ----------------
__device__ __half g_Bh[(size_t)NTOT * K2];                 // B rounded once to fp16
__device__ float  g_part[(size_t)SPLITK * MTOT * NTOT];    // [s][m][n]

// ---------------- SMEM layout ----------------
// per stage: A 16K | B 32K = 48K; 4 stages = 192K
#define OFF_A   0
#define OFF_B   16384
#define STAGE_BYTES 49152
#define SMEM_TOTAL (NSTAGE * STAGE_BYTES)   // 196608

// ---------------- helpers ----------------
static __device__ __forceinline__ void cpa16(uint32_t dst, const void* src) {
    asm volatile("cp.async.cg.shared.global [%0], [%1], 16;\n" :: "r"(dst), "l"(src));
}
static __device__ __forceinline__ void cp_commit() {
    asm volatile("cp.async.commit_group;\n" ::: "memory");
}

static __device__ __forceinline__ void ldsm4(uint32_t (&r)[4], uint32_t addr) {
    asm volatile("ldmatrix.sync.aligned.m8n8.x4.shared.b16 {%0,%1,%2,%3}, [%4];"
                 : "=r"(r[0]), "=r"(r[1]), "=r"(r[2]), "=r"(r[3]) : "r"(addr));
}

static __device__ __forceinline__ void mma16816(float (&d)[4], const uint32_t (&a)[4],
                                                uint32_t b0, uint32_t b1) {
    asm volatile("mma.sync.aligned.m16n8k16.row.col.f32.f16.f16.f32 "
                 "{%0,%1,%2,%3}, {%4,%5,%6,%7}, {%8,%9}, {%0,%1,%2,%3};"
                 : "+f"(d[0]), "+f"(d[1]), "+f"(d[2]), "+f"(d[3])
                 : "r"(a[0]), "r"(a[1]), "r"(a[2]), "r"(a[3]), "r"(b0), "r"(b1));
}

static __device__ __forceinline__ uint32_t pack_h2(float lo, float hi) {
    uint32_t r;
    asm("cvt.rn.f16x2.f32 %0, %1, %2;" : "=r"(r) : "f"(hi), "f"(lo));
    return r;
}

// ---------------- kernel 0: B fp32 -> fp16 (single rounding, 16B out/thread) --
__global__ void __launch_bounds__(256)
convertB_kernel(const float* __restrict__ src, int n8) {
    int i = blockIdx.x * blockDim.x + threadIdx.x;
    if (i >= n8) return;
    float4 v0 = reinterpret_cast<const float4*>(src)[2 * i];
    float4 v1 = reinterpret_cast<const float4*>(src)[2 * i + 1];
    uint4 o;
    o.x = pack_h2(v0.x, v0.y);
    o.y = pack_h2(v0.z, v0.w);
    o.z = pack_h2(v1.x, v1.y);
    o.w = pack_h2(v1.z, v1.w);
    reinterpret_cast<uint4*>(g_Bh)[i] = o;
}

// ---------------- A loader pieces (fp32 LDG -> regs -> cvt -> STS) ----------
static __device__ __forceinline__ void loadA_regs(float4 (&av)[8],
                                                  const float* __restrict__ pA, int tid) {
    #pragma unroll
    for (int i = 0; i < 4; i++) {
        const int idx = i * 256 + tid;
        const int row = idx >> 3, c = idx & 7;
        const float* src = pA + (size_t)row * K2 + c * 8;
        av[2 * i]     = *reinterpret_cast<const float4*>(src);
        av[2 * i + 1] = *reinterpret_cast<const float4*>(src + 4);
    }
}
static __device__ __forceinline__ void storeA_smem(const float4 (&av)[8],
                                                   uint32_t stb, int tid) {
    #pragma unroll
    for (int i = 0; i < 4; i++) {
        const int idx = i * 256 + tid;
        const int row = idx >> 3, c = idx & 7;
        const uint32_t r0 = pack_h2(av[2 * i].x,     av[2 * i].y);
        const uint32_t r1 = pack_h2(av[2 * i].z,     av[2 * i].w);
        const uint32_t r2 = pack_h2(av[2 * i + 1].x, av[2 * i + 1].y);
        const uint32_t r3 = pack_h2(av[2 * i + 1].z, av[2 * i + 1].w);
        const uint32_t dst = stb + OFF_A + (uint32_t)(row * 128 + ((c ^ (row & 7)) << 4));
        asm volatile("st.shared.v4.b32 [%0], {%1,%2,%3,%4};"
                     :: "r"(dst), "r"(r0), "r"(r1), "r"(r2), "r"(r3));
    }
}

// B per stage: 2048 x 16B chunks via cp.async; 8/thread; one commit group per stage.
static __device__ __forceinline__ void loadB_stage(uint32_t stb,
                                                   const __half* __restrict__ pB, int tid) {
    #pragma unroll
    for (int i = 0; i < 8; i++) {
        const int rem = i * 256 + tid;
        const int row = rem >> 3, c = rem & 7;
        cpa16(stb + OFF_B + (uint32_t)(row * 128 + ((c ^ (row & 7)) << 4)),
              pB + (size_t)row * K2 + c * 8);
    }
    cp_commit();
}

// ---------------- kernel 1: split-K GEMM, fused A convert, 4-stage, 1 barrier -
__global__ void __launch_bounds__(256, 1)
gemm_mma_kernel(const float* __restrict__ Afp32)
{
    extern __shared__ char smem[];
    const uint32_t sb = (uint32_t)__cvta_generic_to_shared(smem);
    const int tid  = threadIdx.x;
    const int lane = tid & 31;
    const int wid  = tid >> 5;
    const int wm   = (wid >> 2) * 64;    // 2 row bands
    const int wn   = (wid & 3) * 64;     // 4 col bands
    const int bm = blockIdx.x, bn = blockIdx.y, s = blockIdx.z;

    const size_t kbase = (size_t)s * KS;
    const float*  pA = Afp32 + (size_t)(bm * BM) * K2 + kbase;
    const __half* pB = g_Bh  + (size_t)(bn * BN) * K2 + kbase;

    float acc[4][8][4];
    #pragma unroll
    for (int f = 0; f < 4; f++)
        #pragma unroll
        for (int j = 0; j < 8; j++)
            #pragma unroll
            for (int r = 0; r < 4; r++) acc[f][j][r] = 0.0f;

    // prologue: stages 0..2 (B via 3 ordered commit groups; A direct LDG+STS)
    loadB_stage(sb,                   pB,          tid);
    loadB_stage(sb + STAGE_BYTES,     pB + BK,     tid);
    loadB_stage(sb + 2 * STAGE_BYTES, pB + 2 * BK, tid);
    {
        float4 av[8];
        loadA_regs(av, pA, tid);          storeA_smem(av, sb, tid);
        loadA_regs(av, pA + BK, tid);     storeA_smem(av, sb + STAGE_BYTES, tid);
        loadA_regs(av, pA + 2 * BK, tid); storeA_smem(av, sb + 2 * STAGE_BYTES, tid);
    }

    const int lr = lane & 15;     // ldmatrix row within 16
    const int lc = lane >> 4;     // ldmatrix k-half

    for (int it = 0; it < NIT; ++it) {
        const bool ld = (it + 3) < NIT;

        // A fp32 loads for stage it+3 (gmem->regs; consumed after compute)
        float4 av[8];
        if (ld) loadA_regs(av, pA + (size_t)(it + 3) * BK, tid);

        // B of stage it complete: outstanding groups = it, it+1, it+2 -> allow 2
        asm volatile("cp.async.wait_group 2;\n" ::: "memory");
        __syncthreads();   // single barrier per iteration (after wait: cross-thread vis)

        const uint32_t stb = sb + (uint32_t)(it & 3) * STAGE_BYTES;

        #pragma unroll
        for (int kk = 0; kk < 4; kk++) {          // 4 x k16 per stage
            const int c = kk * 2 + lc;
            uint32_t aH[4][4], bH[4][4];
            #pragma unroll
            for (int f = 0; f < 4; f++) {
                const int row = wm + f * 16 + lr;
                ldsm4(aH[f], stb + OFF_A + (uint32_t)(row * 128 + ((c ^ (row & 7)) << 4)));
            }
            #pragma unroll
            for (int g = 0; g < 4; g++) {
                const int row = wn + g * 16 + lr;
                ldsm4(bH[g], stb + OFF_B + (uint32_t)(row * 128 + ((c ^ (row & 7)) << 4)));
            }
            #pragma unroll
            for (int f = 0; f < 4; f++)
                #pragma unroll
                for (int j = 0; j < 8; j++)
                    mma16816(acc[f][j], aH[f], bH[j >> 1][j & 1], bH[j >> 1][(j & 1) + 2]);
        }

        // store/load tail: buffer (it+3)%4 == (it-1)%4, last read in iter it-1,
        // protected by this iteration's top barrier. No trailing barrier: each
        // warp's tail overlaps other warps' compute.
        if (ld) {
            const uint32_t wtb = sb + (uint32_t)((it + 3) & 3) * STAGE_BYTES;
            storeA_smem(av, wtb, tid);
            loadB_stage(wtb, pB + (size_t)(it + 3) * BK, tid);  // 1 commit group
        } else {
            cp_commit();   // keep group accounting uniform
        }
    }

    // store partials: [s][m][n]
    float* base = g_part + ((size_t)s * MTOT + (size_t)bm * BM) * NTOT + bn * BN;
    #pragma unroll
    for (int f = 0; f < 4; f++) {
        const int r0 = wm + f * 16 + (lane >> 2);
        #pragma unroll
        for (int j = 0; j < 8; j++) {
            const int n0 = wn + j * 8 + (lane & 3) * 2;
            *reinterpret_cast<float2*>(&base[(size_t)r0 * NTOT + n0]) =
                make_float2(acc[f][j][0], acc[f][j][1]);
            *reinterpret_cast<float2*>(&base[(size_t)(r0 + 8) * NTOT + n0]) =
                make_float2(acc[f][j][2], acc[f][j][3]);
        }
    }
}

// ---------------- kernel 2: split-K reduce + bias + einsum (float4) ---------
__global__ void __launch_bounds__(256)
epilogue_kernel(const float* __restrict__ x_all,   // output [64][12][1024][64]
                const float* __restrict__ b_hyp,   // [768]
                float* __restrict__ out)           // [64][12][1024]
{
    __shared__ float4 sh_h4[HORIZON * 17];   // [t][16] pad 17
    __shared__ float4 sh_x4[BATCH * 17];     // [b][16] pad 17

    const int n   = blockIdx.x;   // node (m index of GEMM)
    const int tid = threadIdx.x;

    // h: 192 float4 (768 floats): split-K reduce + bias
    if (tid < 192) {
        float4 a = reinterpret_cast<const float4*>(b_hyp)[tid];
        #pragma unroll
        for (int sp = 0; sp < SPLITK; sp++) {
            float4 v = *reinterpret_cast<const float4*>(
                &g_part[((size_t)sp * MTOT + n) * NTOT + tid * 4]);
            a.x += v.x; a.y += v.y; a.z += v.z; a.w += v.w;
        }
        sh_h4[(tid >> 4) * 17 + (tid & 15)] = a;
    }

    // x: 1024 float4 (64 b x 16 fc)
    #pragma unroll
    for (int r = 0; r < 4; r++) {
        const int i = tid + 256 * r;          // 0..1023
        const int b = i >> 4, fc = i & 15;
        sh_x4[b * 17 + fc] = *reinterpret_cast<const float4*>(
            &x_all[((size_t)(b * T_IN + (T_IN - 1)) * MTOT + n) * 64 + fc * 4]);
    }
    __syncthreads();

    #pragma unroll
    for (int r = 0; r < 3; r++) {
        const int j = tid + 256 * r;          // 0..767
        const int b = j / 12, t = j % 12;
        float acc = 0.0f;
        #pragma unroll
        for (int fc = 0; fc < 16; fc++) {
            const float4 xv = sh_x4[b * 17 + fc];
            const float4 hv = sh_h4[t * 17 + fc];
            acc += xv.x * hv.x + xv.y * hv.y + xv.z * hv.z + xv.w * hv.w;
        }
        out[(size_t)(b * HORIZON + t) * MTOT + n] = acc;
    }
}

// ---------------- launch ----------------
extern "C" void kernel_launch(void* const* d_in, const int* in_sizes, int n_in,
                              void* d_out, int out_size) {
    const float* output  = (const float*)d_in[0];   // [64,12,1024,64]
    const float* weights = (const float*)d_in[1];   // [1024,36864]
    const float* W_hyp   = (const float*)d_in[2];   // [768,36864]
    const float* b_hyp   = (const float*)d_in[3];   // [768]
    float* out = (float*)d_out;

    cudaFuncSetAttribute(gemm_mma_kernel,
                         cudaFuncAttributeMaxDynamicSharedMemorySize, SMEM_TOTAL);

    const int nB8 = NTOT * K2 / 8;   // 3538944
    convertB_kernel<<<(nB8 + 255) / 256, 256>>>(W_hyp, nB8);

    dim3 grid(MTOT / BM, NTOT / BN, SPLITK);   // (8, 3, 6) = 144 CTAs
    gemm_mma_kernel<<<grid, 256, SMEM_TOTAL>>>(weights);

    epilogue_kernel<<<MTOT, 256>>>(output, b_hyp, out);
}